// round 4
// baseline (speedup 1.0000x reference)
#include <cuda_runtime.h>
#include <cstdint>

// Static config (Fp8Padding num_gemms=8, align=16)
// M_SPLITS       = {4091, 8177, 2045, 4093, 6133, 1021, 4085, 8189}
// PADDED_SPLITS  = {4096, 8192, 2048, 4096, 6144, 1024, 4096, 8192}
// HIDDEN = 2048 floats = 8192 bytes per row
//
// Key observation: both input segments and output segments are CONTIGUOUS.
// The whole op = 8 big D2D block copies + zero-filling 54 pad rows.

#define HIDDEN4      512                     // float4 per row
#define ROW_BYTES    (2048 * 4)              // 8192
#define N_PAD_ROWS   54                      // total alignment pad rows

// First output row of each pad run and its length (tail of each segment):
//   seg:        0      1      2      3      4      5      6      7
//   pad start:  4091  12273  16381  22525  24565  25597  29685  37885
//   pad len:    5     15     3      3      11     3      11     3
__constant__ int c_pad_row[N_PAD_ROWS] = {
    4091, 4092, 4093, 4094, 4095,
    12273, 12274, 12275, 12276, 12277, 12278, 12279, 12280, 12281, 12282,
    12283, 12284, 12285, 12286, 12287,
    16381, 16382, 16383,
    22525, 22526, 22527,
    24565, 24566, 24567, 24568, 24569, 24570, 24571, 24572, 24573, 24574, 24575,
    25597, 25598, 25599,
    29685, 29686, 29687, 29688, 29689, 29690, 29691, 29692, 29693, 29694, 29695,
    37885, 37886, 37887
};

// Zero the 54 pad rows: one block per pad row, 256 threads x 2 float4.
__global__ void __launch_bounds__(256) zero_pad_rows_kernel(float4* __restrict__ out)
{
    int row = c_pad_row[blockIdx.x];
    float4 z = make_float4(0.f, 0.f, 0.f, 0.f);
    float4* p = out + (long long)row * HIDDEN4 + threadIdx.x;
    p[0]   = z;
    p[256] = z;
}

extern "C" void kernel_launch(void* const* d_in, const int* in_sizes, int n_in,
                              void* d_out, int out_size)
{
    const char* in  = (const char*)d_in[0];
    char*       out = (char*)d_out;

    // Zero pad rows first (tiny, 0.44 MB).
    zero_pad_rows_kernel<<<N_PAD_ROWS, 256>>>((float4*)d_out);

    // 8 contiguous segment copies (row offsets precomputed, in bytes).
    static const long long in_row [8] = {0, 4091, 12268, 14313, 18406, 24539, 25560, 29645};
    static const long long out_row[8] = {0, 4096, 12288, 14336, 18432, 24576, 25600, 29696};
    static const long long m_rows [8] = {4091, 8177, 2045, 4093, 6133, 1021, 4085, 8189};

    for (int s = 0; s < 8; s++) {
        cudaMemcpyAsync(out + out_row[s] * ROW_BYTES,
                        in  + in_row [s] * ROW_BYTES,
                        m_rows[s] * ROW_BYTES,
                        cudaMemcpyDeviceToDevice, 0);
    }
}

// round 5
// speedup vs baseline: 1.1785x; 1.1785x over previous
#include <cuda_runtime.h>
#include <cstdint>

// Static config (Fp8Padding num_gemms=8, align=16)
// M_SPLITS       = {4091, 8177, 2045, 4093, 6133, 1021, 4085, 8189}
// PADDED_SPLITS  = {4096, 8192, 2048, 4096, 6144, 1024, 4096, 8192}
// HIDDEN = 2048 floats = 512 float4 per row

#define HIDDEN4     512                      // float4 per row
#define TOTAL_OUT4  (37888 * HIDDEN4)        // 19,398,656 float4
#define VPT         4                        // float4 per thread
#define TPB         256
#define CHUNK       (TPB * VPT)              // 1024 float4 per block

__constant__ int c_out_start[8] = {0, 4096, 12288, 14336, 18432, 24576, 25600, 29696};
__constant__ int c_in_start [8] = {0, 4091, 12268, 14313, 18406, 24539, 25560, 29645};
__constant__ int c_m        [8] = {4091, 8177, 2045, 4093, 6133, 1021, 4085, 8189};

__global__ void __launch_bounds__(TPB) fp8_padding_kernel(
    const float4* __restrict__ in, float4* __restrict__ out)
{
    int base = blockIdx.x * CHUNK + threadIdx.x;

    // Precompute all 4 source offsets + predicates first so ptxas can
    // front-batch the 4 independent LDG.128s (MLP_p1 = 4).
    long long src_off[VPT];
    bool      valid[VPT];
    #pragma unroll
    for (int k = 0; k < VPT; k++) {
        int idx = base + k * TPB;
        int row = idx >> 9;
        int col = idx & (HIDDEN4 - 1);

        int seg = (row >= 4096)  + (row >= 12288) + (row >= 14336) + (row >= 18432)
                + (row >= 24576) + (row >= 25600) + (row >= 29696);

        int local = row - c_out_start[seg];
        valid[k]   = (local < c_m[seg]);
        src_off[k] = (long long)(c_in_start[seg] + local) * HIDDEN4 + col;
    }

    float4 v[VPT];
    #pragma unroll
    for (int k = 0; k < VPT; k++) {
        v[k] = make_float4(0.f, 0.f, 0.f, 0.f);
        if (valid[k])
            v[k] = __ldcs(&in[src_off[k]]);      // streaming (evict-first) load
    }

    #pragma unroll
    for (int k = 0; k < VPT; k++) {
        __stcs(&out[base + k * TPB], v[k]);      // streaming (evict-first) store
    }
}

extern "C" void kernel_launch(void* const* d_in, const int* in_sizes, int n_in,
                              void* d_out, int out_size)
{
    const float4* in  = (const float4*)d_in[0];
    float4*       out = (float4*)d_out;
    // TOTAL_OUT4 = 19,398,656 = 18,944 * 1024 exactly
    fp8_padding_kernel<<<TOTAL_OUT4 / CHUNK, TPB>>>(in, out);
}